// round 3
// baseline (speedup 1.0000x reference)
#include <cuda_runtime.h>
#include <cstdint>

// NearestNeighborGraph: 16 samples x 2048 points x 64 dims, K=16.
// Output layout (float32): [knn_dist (16*2048*16) | dst (16*2048*16) | src (16*2048*16)]
//
// Strategy:
//  - Prologue kernel: per-point squared norms into __device__ scratch (no allocs).
//  - Main kernel: CTA = 128 threads = 128 query rows. Candidate tile (128x64 f32)
//    staged in SMEM; broadcast reads (all lanes read the same candidate row ->
//    conflict-free). Query vector lives in registers as packed f32x2 pairs; the
//    dot product uses sm_103a packed fma.rn.f32x2 to halve FFMA issue count.
//  - Top-16 kept as a sorted register list; strict '<' insertion + single bubble
//    pass reproduces jax.lax.top_k's stable ordering (ascending distance, ties
//    broken by smaller index).

#define NS   16
#define NP   2048
#define DIMS 64
#define KNN  16
#define BM   128
#define BN   128
#define OUTBLK (NS * NP * KNN)   // 524288

__device__ float g_x2[NS * NP];  // per-point squared norms (scratch, no alloc)

#define FMA2(acc, x, y) \
    asm("fma.rn.f32x2 %0, %1, %2, %0;" : "+l"(acc) : "l"(x), "l"(y))
#define ADD2(d, a, b) \
    asm("add.rn.f32x2 %0, %1, %2;" : "=l"(d) : "l"(a), "l"(b))

__global__ void __launch_bounds__(256) norms_kernel(const float* __restrict__ h) {
    int p = blockIdx.x * blockDim.x + threadIdx.x;
    if (p >= NS * NP) return;
    const float4* hp = reinterpret_cast<const float4*>(h + (size_t)p * DIMS);
    float s = 0.f;
#pragma unroll
    for (int k = 0; k < DIMS / 4; ++k) {
        float4 v = hp[k];
        s += v.x * v.x;
        s += v.y * v.y;
        s += v.z * v.z;
        s += v.w * v.w;
    }
    g_x2[p] = s;
}

__global__ void __launch_bounds__(BM, 2) knn_kernel(const float* __restrict__ h,
                                                    float* __restrict__ out,
                                                    int write_edges) {
    __shared__ float tile[BN * DIMS];   // 32 KB candidate tile
    __shared__ float cn[BN];            // candidate norms

    const int b  = blockIdx.y;
    const int i  = blockIdx.x * BM + threadIdx.x;
    const int gi = b * NP + i;

    // Query vector -> 32 packed f32x2 registers (h is 16B-aligned, row = 256B).
    unsigned long long q[DIMS / 2];
    {
        const ulonglong2* qp = reinterpret_cast<const ulonglong2*>(h + (size_t)gi * DIMS);
#pragma unroll
        for (int k = 0; k < DIMS / 4; ++k) {
            ulonglong2 v = qp[k];
            q[2 * k]     = v.x;
            q[2 * k + 1] = v.y;
        }
    }
    const float qn = g_x2[gi];

    // Sorted top-K list (ascending distance).
    float dk[KNN];
    int   ik[KNN];
#pragma unroll
    for (int k = 0; k < KNN; ++k) { dk[k] = 3.4e38f; ik[k] = 0; }

    const float* hb = h + (size_t)b * NP * DIMS;

    for (int jt = 0; jt < NP; jt += BN) {
        __syncthreads();
        {
            // Coalesced tile load: 128x64 floats, flat float4 copy.
            const float4* s4 = reinterpret_cast<const float4*>(hb + (size_t)jt * DIMS);
            float4*       d4 = reinterpret_cast<float4*>(tile);
#pragma unroll
            for (int k = 0; k < (BN * DIMS / 4) / BM; ++k)
                d4[threadIdx.x + k * BM] = s4[threadIdx.x + k * BM];
            cn[threadIdx.x] = g_x2[b * NP + jt + threadIdx.x];
        }
        __syncthreads();

        for (int j = 0; j < BN; ++j) {
            // All lanes read the same candidate row: SMEM broadcast, conflict-free.
            const ulonglong2* cp =
                reinterpret_cast<const ulonglong2*>(&tile[j * DIMS]);
            unsigned long long a0 = 0ull, a1 = 0ull, a2 = 0ull, a3 = 0ull;
#pragma unroll
            for (int k = 0; k < DIMS / 4; k += 2) {
                ulonglong2 c0 = cp[k];
                ulonglong2 c1 = cp[k + 1];
                FMA2(a0, q[2 * k],     c0.x);
                FMA2(a1, q[2 * k + 1], c0.y);
                FMA2(a2, q[2 * k + 2], c1.x);
                FMA2(a3, q[2 * k + 3], c1.y);
            }
            ADD2(a0, a0, a1);
            ADD2(a2, a2, a3);
            ADD2(a0, a0, a2);
            float lo, hi;
            asm("mov.b64 {%0,%1}, %2;" : "=f"(lo), "=f"(hi) : "l"(a0));
            float dot = lo + hi;
            float d   = fmaf(-2.f, dot, qn + cn[j]);

            // Strict '<' keeps the earlier index on ties (stable like lax.top_k).
            if (d < dk[KNN - 1]) {
                dk[KNN - 1] = d;
                ik[KNN - 1] = jt + j;
#pragma unroll
                for (int t = KNN - 1; t > 0; --t) {
                    if (dk[t] < dk[t - 1]) {
                        float td = dk[t]; dk[t] = dk[t - 1]; dk[t - 1] = td;
                        int   ti = ik[t]; ik[t] = ik[t - 1]; ik[t - 1] = ti;
                    }
                }
            }
        }
    }

    // Emit results.
    float* od = out + (size_t)gi * KNN;
#pragma unroll
    for (int k = 0; k < KNN; ++k) od[k] = dk[k];

    if (write_edges) {
        float* odst = out + OUTBLK + (size_t)gi * KNN;
        float* osrc = out + 2 * OUTBLK + (size_t)gi * KNN;
        const float fsrc = (float)gi;  // src = i + b*NP, globally offset
#pragma unroll
        for (int k = 0; k < KNN; ++k) {
            odst[k] = (float)(ik[k] + b * NP);
            osrc[k] = fsrc;
        }
    }
}

extern "C" void kernel_launch(void* const* d_in, const int* in_sizes, int n_in,
                              void* d_out, int out_size) {
    const float* h   = (const float*)d_in[0];
    float*       out = (float*)d_out;
    const int write_edges = (out_size >= 3 * OUTBLK) ? 1 : 0;

    norms_kernel<<<(NS * NP + 255) / 256, 256>>>(h);
    dim3 grid(NP / BM, NS);
    knn_kernel<<<grid, BM>>>(h, out, write_edges);
}